// round 15
// baseline (speedup 1.0000x reference)
#include <cuda_runtime.h>

// Problem shape (fixed by dataset instance)
#define B_   8
#define H_   96
#define W_   320
#define HWp  (H_ * W_)            // 30720
#define NPIX (B_ * HWp)           // 245760
#define VOL_ELEMS (B_ * 45 * HWp) // 11059200
#define INTERVAL (4.0f / 7.0f)
#define NVOLB  1920               // vol blocks (NPIX/128)
#define NDISPB 480                // disp blocks (NPIX/4/128)

// Sample one pyramid level from a register window w[0..9] (w[i] = level[F-4+i]).
// R10's proven numerics, unchanged.
__device__ __forceinline__ void sample_level(const float w[10],
                                             float Ff, float center, float w1m1,
                                             float stdv, float* __restrict__ outL)
{
    const int EL[8] = {0, 0, 1, 1, 2, 2, 3, 4};   // floor(s*4/7)
    float fm4 = __fsub_rn(Ff, 4.0f);
    float cm4 = __fsub_rn(center, 4.0f);
    float cp4 = __fadd_rn(center, 4.0f);

    #pragma unroll
    for (int s8 = 0; s8 < 8; ++s8) {
        const int e = EL[s8];
        float offs = __fmul_rn((float)s8, INTERVAL);

        // LEFT: floor(lc) in {F-4+e, F-4+e+1}; pick via exact float compare.
        float lc   = __fadd_rn(cm4, offs);
        float bnd0 = __fadd_rn(fm4, (float)e);
        float bnd1 = __fadd_rn(fm4, (float)(e + 1));
        bool  bl   = lc >= bnd1;
        float a    = bl ? w[e + 1] : w[e];
        float bb   = bl ? w[e + 2] : w[e + 1];
        float wt   = __fsub_rn(lc, bl ? bnd1 : bnd0);
        float v    = __fmaf_rn(wt, __fsub_rn(bb, a), a);
        outL[s8 * HWp] = (lc > 0.0f) ? v : 0.0f;

        // RIGHT: sample s -> channel 14-s; floor(c) in {F+3-e, F+4-e}.
        if (s8 < 7) {
            float rc = __fsub_rn(cp4, offs);
            float dn = __fsub_rn(stdv, rc);
            float c  = fminf(rc, w1m1);
            float r0 = __fadd_rn(Ff, (float)(3 - e));
            float r1 = __fadd_rn(Ff, (float)(4 - e));
            bool  br = c >= r1;
            float ar  = br ? w[8 - e] : w[7 - e];
            float bbr = br ? w[9 - e] : w[8 - e];
            float wr  = __fsub_rn(c, br ? r1 : r0);
            float vr  = __fmaf_rn(wr, __fsub_rn(bbr, ar), ar);
            outL[(14 - s8) * HWp] = (dn > 0.0f && dn < w1m1) ? vr : 0.0f;
        }
    }
}

__global__ void __launch_bounds__(128, 9)
pcv_kernel(const float* __restrict__ corr,
           const float* __restrict__ disp,
           float* __restrict__ out)
{
    int bid = blockIdx.x;
    int t   = threadIdx.x;

    // ---- Disp-writer blocks (interleaved 1-in-5): closed-form, float4 stores ----
    if (bid % 5 == 4) {
        int g  = (bid / 5) * 128 + t;          // quad index in [0, NPIX/4)
        int x4 = g % (W_ / 4);
        int bh = g / (W_ / 4);
        int x  = 4 * x4;
        float4 d4 = *reinterpret_cast<const float4*>(disp + bh * W_ + x);
        int b = bh / H_;
        int h = bh - b * H_;
        float* dst = out + VOL_ELEMS + ((size_t)(b * 45) * H_ + h) * W_ + x;
        #pragma unroll
        for (int lv = 0; lv < 3; ++lv) {
            float inv = (lv == 0) ? 1.0f : (lv == 1) ? 0.5f : 0.25f;
            float4 dl;
            dl.x = __fmul_rn(d4.x, inv); dl.y = __fmul_rn(d4.y, inv);
            dl.z = __fmul_rn(d4.z, inv); dl.w = __fmul_rn(d4.w, inv);
            #pragma unroll
            for (int c = 0; c < 15; ++c) {
                float kk = __fmul_rn((float)(c - 7), INTERVAL);
                float4 v;
                v.x = __fadd_rn(kk, dl.x); v.y = __fadd_rn(kk, dl.y);
                v.z = __fadd_rn(kk, dl.z); v.w = __fadd_rn(kk, dl.w);
                *reinterpret_cast<float4*>(dst + (size_t)(lv * 15 + c) * HWp) = v;
            }
        }
        return;
    }

    // ---- Vol blocks ----
    // Single staging buffer: 45-float stride per pixel (gcd(45,32)=1 ->
    // conflict-clean scalar readback). 22.5 KB -> 9 blocks fit in smem.
    __shared__ float stageS[128 * 45];

    int lane = t & 31;
    int warp = t >> 5;

    int vbid = (bid / 5) * 4 + (bid % 5);   // [0, 1920)
    int idx  = vbid * 128 + t;

    int x  = idx % W_;
    int bh = idx / W_;
    float d  = __ldg(disp + idx);
    float fx = (float)x;

    // centers per level: clip(x/2^i - d/2^i, 0, w1-1)
    float c0 = fminf(fmaxf(__fsub_rn(fx, d), 0.0f), 319.0f);
    float c1 = fminf(fmaxf(__fsub_rn(__fmul_rn(fx, 0.5f),  __fmul_rn(d, 0.5f)),  0.0f), 159.0f);
    float c2 = fminf(fmaxf(__fsub_rn(__fmul_rn(fx, 0.25f), __fmul_rn(d, 0.25f)), 0.0f), 79.0f);

    float F0 = floorf(c0), F1 = floorf(c1), F2 = floorf(c2);
    int iF0 = (int)F0, iF1 = (int)F1, iF2 = (int)F2;

    int J2lo = max(0, iF2 - 4);
    int J2hi = min(79, (int)ceilf(c2) + 4);
    int n4   = J2hi - J2lo;                 // 4..9
    int J1lo = max(0, iF1 - 4);
    int R0   = 4 * J2lo;

    // ---- Cooperative warp gather: lanes fetch consecutive float4s of the same
    // pixel's window (contiguous lines; ~7 lines/instr instead of 32).
    // (pixel, j) = (lin/10, lin%10); per-target params via shfl. All 10 slots of
    // every pixel get written (clamped source) -> staging is always finite.
    float* stw = stageS + warp * (32 * 45);
    unsigned pk = (unsigned)J2lo | ((unsigned)n4 << 8);
    int pix0 = vbid * 128 + (t & ~31);
    const float4* corr4 = reinterpret_cast<const float4*>(corr);

    #pragma unroll
    for (int it = 0; it < 10; ++it) {
        int lin = it * 32 + lane;           // 0..319
        int p   = lin / 10;
        int j   = lin - p * 10;
        unsigned pkp = __shfl_sync(0xffffffffu, pk, p);
        int J2p = (int)(pkp & 0xffu);
        int n4p = (int)(pkp >> 8);
        float4 v = __ldcs(corr4 + (size_t)(pix0 + p) * (W_ / 4) + (J2p + min(j, n4p)));
        float* dst = stw + p * 45 + 4 * j;
        dst[0] = v.x; dst[1] = v.y; dst[2] = v.z; dst[3] = v.w;
    }
    __syncwarp();

    const float* stf = stw + lane * 45;     // this thread's 40 raw floats

    int b = bh / H_;
    int h = bh - b * H_;
    int volBase = (b * 45 * H_ + h) * W_ + x;

    // ---- Level 0: window straight from staged raw ----
    // Upper clamp provably redundant: o0+9 = iF0+5-R0 <= 4*n4+3 <= 39.
    {
        int o0 = iF0 - 4 - R0;
        float w0_[10];
        #pragma unroll
        for (int i = 0; i < 10; ++i)
            w0_[i] = stf[max(o0 + i, 0)];
        sample_level(w0_, F0, c0, 319.0f, fx, out + volBase);
    }

    // ---- Level 1: pool pairs on the fly ----
    // Upper clamp provably redundant: o1+18+1 = 2*iF1+11-R0 <= 4*n4+3.
    {
        int o1 = 2 * (iF1 - 4) - R0;        // even; pairs (u, u+1)
        float w1_[10];
        #pragma unroll
        for (int i = 0; i < 10; ++i) {
            int u = max(o1 + 2 * i, 0);
            w1_[i] = __fmul_rn(__fadd_rn(stf[u], stf[u + 1]), 0.5f);
        }
        sample_level(w1_, F1, c1, 159.0f, __fmul_rn(fx, 0.5f), out + volBase + 15 * HWp);
    }

    // ---- Level 2: pairwise pool of 4 raw floats per slot ----
    {
        int o2 = iF2 - 4 - J2lo;            // in [-4, 0]
        float w2_[10];
        #pragma unroll
        for (int i = 0; i < 10; ++i) {
            int gg = max(o2 + i, 0);        // <= 9 always
            float s0 = __fmul_rn(__fadd_rn(stf[4*gg+0], stf[4*gg+1]), 0.5f);
            float s1 = __fmul_rn(__fadd_rn(stf[4*gg+2], stf[4*gg+3]), 0.5f);
            w2_[i] = __fmul_rn(__fadd_rn(s0, s1), 0.5f);
        }
        sample_level(w2_, F2, c2, 79.0f, __fmul_rn(fx, 0.25f), out + volBase + 30 * HWp);
    }
}

extern "C" void kernel_launch(void* const* d_in, const int* in_sizes, int n_in,
                              void* d_out, int out_size)
{
    const float* corr = (const float*)d_in[0];   // cross_attention [8,96,320,320]
    const float* disp = (const float*)d_in[1];   // cur_disp [8,1,96,320]
    float* out = (float*)d_out;                  // [vol ; disps], each [8,45,96,320]
    pcv_kernel<<<NVOLB + NDISPB, 128>>>(corr, disp, out);
}

// round 16
// speedup vs baseline: 1.0370x; 1.0370x over previous
#include <cuda_runtime.h>

// Problem shape (fixed by dataset instance)
#define B_   8
#define H_   96
#define W_   320
#define HWp  (H_ * W_)            // 30720
#define NPIX (B_ * HWp)           // 245760
#define VOL_ELEMS (B_ * 45 * HWp) // 11059200
#define INTERVAL (4.0f / 7.0f)
#define NVOLB  1920               // vol blocks (NPIX/128)
#define NDISPB 480                // disp blocks (NPIX/4/128)

// Sample one pyramid level from a register window w[0..9] (w[i] = level[F-4+i]).
// R10's proven numerics, unchanged.
__device__ __forceinline__ void sample_level(const float w[10],
                                             float Ff, float center, float w1m1,
                                             float stdv, float* __restrict__ outL)
{
    const int EL[8] = {0, 0, 1, 1, 2, 2, 3, 4};   // floor(s*4/7)
    float fm4 = __fsub_rn(Ff, 4.0f);
    float cm4 = __fsub_rn(center, 4.0f);
    float cp4 = __fadd_rn(center, 4.0f);

    #pragma unroll
    for (int s8 = 0; s8 < 8; ++s8) {
        const int e = EL[s8];
        float offs = __fmul_rn((float)s8, INTERVAL);

        // LEFT: floor(lc) in {F-4+e, F-4+e+1}; pick via exact float compare.
        float lc   = __fadd_rn(cm4, offs);
        float bnd0 = __fadd_rn(fm4, (float)e);
        float bnd1 = __fadd_rn(fm4, (float)(e + 1));
        bool  bl   = lc >= bnd1;
        float a    = bl ? w[e + 1] : w[e];
        float bb   = bl ? w[e + 2] : w[e + 1];
        float wt   = __fsub_rn(lc, bl ? bnd1 : bnd0);
        float v    = __fmaf_rn(wt, __fsub_rn(bb, a), a);
        outL[s8 * HWp] = (lc > 0.0f) ? v : 0.0f;

        // RIGHT: sample s -> channel 14-s; floor(c) in {F+3-e, F+4-e}.
        if (s8 < 7) {
            float rc = __fsub_rn(cp4, offs);
            float dn = __fsub_rn(stdv, rc);
            float c  = fminf(rc, w1m1);
            float r0 = __fadd_rn(Ff, (float)(3 - e));
            float r1 = __fadd_rn(Ff, (float)(4 - e));
            bool  br = c >= r1;
            float ar  = br ? w[8 - e] : w[7 - e];
            float bbr = br ? w[9 - e] : w[8 - e];
            float wr  = __fsub_rn(c, br ? r1 : r0);
            float vr  = __fmaf_rn(wr, __fsub_rn(bbr, ar), ar);
            outL[(14 - s8) * HWp] = (dn > 0.0f && dn < w1m1) ? vr : 0.0f;
        }
    }
}

__global__ void __launch_bounds__(128, 8)
pcv_kernel(const float* __restrict__ corr,
           const float* __restrict__ disp,
           float* __restrict__ out)
{
    int bid = blockIdx.x;
    int t   = threadIdx.x;

    // ---- Disp-writer blocks (interleaved 1-in-5): closed-form, float4 stores ----
    if (bid % 5 == 4) {
        int g  = (bid / 5) * 128 + t;          // quad index in [0, NPIX/4)
        int x4 = g % (W_ / 4);
        int bh = g / (W_ / 4);
        int x  = 4 * x4;
        float4 d4 = *reinterpret_cast<const float4*>(disp + bh * W_ + x);
        int b = bh / H_;
        int h = bh - b * H_;
        float* dst = out + VOL_ELEMS + ((size_t)(b * 45) * H_ + h) * W_ + x;
        #pragma unroll
        for (int lv = 0; lv < 3; ++lv) {
            float inv = (lv == 0) ? 1.0f : (lv == 1) ? 0.5f : 0.25f;
            float4 dl;
            dl.x = __fmul_rn(d4.x, inv); dl.y = __fmul_rn(d4.y, inv);
            dl.z = __fmul_rn(d4.z, inv); dl.w = __fmul_rn(d4.w, inv);
            #pragma unroll
            for (int c = 0; c < 15; ++c) {
                float kk = __fmul_rn((float)(c - 7), INTERVAL);
                float4 v;
                v.x = __fadd_rn(kk, dl.x); v.y = __fadd_rn(kk, dl.y);
                v.z = __fadd_rn(kk, dl.z); v.w = __fadd_rn(kk, dl.w);
                *reinterpret_cast<float4*>(dst + (size_t)(lv * 15 + c) * HWp) = v;
            }
        }
        return;
    }

    // ---- Vol blocks ----
    // Single staging buffer: 45-float stride per pixel (gcd(45,32)=1 ->
    // conflict-clean scalar readback). 22.5 KB -> 8 blocks/SM.
    __shared__ float stageS[128 * 45];

    int lane = t & 31;
    int warp = t >> 5;

    int vbid = (bid / 5) * 4 + (bid % 5);   // [0, 1920)
    int idx  = vbid * 128 + t;

    int x  = idx % W_;
    int bh = idx / W_;
    float d  = __ldg(disp + idx);
    float fx = (float)x;

    // centers per level: clip(x/2^i - d/2^i, 0, w1-1)
    float c0 = fminf(fmaxf(__fsub_rn(fx, d), 0.0f), 319.0f);
    float c1 = fminf(fmaxf(__fsub_rn(__fmul_rn(fx, 0.5f),  __fmul_rn(d, 0.5f)),  0.0f), 159.0f);
    float c2 = fminf(fmaxf(__fsub_rn(__fmul_rn(fx, 0.25f), __fmul_rn(d, 0.25f)), 0.0f), 79.0f);

    float F0 = floorf(c0), F1 = floorf(c1), F2 = floorf(c2);
    int iF0 = (int)F0, iF1 = (int)F1, iF2 = (int)F2;

    int J2lo = max(0, iF2 - 4);
    int J2hi = min(79, (int)ceilf(c2) + 4);
    int n4   = J2hi - J2lo;                 // 4..9
    int J1lo = max(0, iF1 - 4);
    int R0   = 4 * J2lo;
    (void)J1lo;

    // ---- Cooperative warp gather: lanes fetch consecutive float4s of the same
    // pixel's window (contiguous lines; ~7 lines/instr instead of 32).
    // (pixel, j) = (lin/10, lin%10); per-target params via shfl. All 10 slots of
    // every pixel get written (clamped source) -> staging is always finite.
    float* stw = stageS + warp * (32 * 45);
    unsigned pk = (unsigned)J2lo | ((unsigned)n4 << 8);
    int pix0 = vbid * 128 + (t & ~31);
    const float4* corr4 = reinterpret_cast<const float4*>(corr);

    #pragma unroll
    for (int it = 0; it < 10; ++it) {
        int lin = it * 32 + lane;           // 0..319
        int p   = lin / 10;
        int j   = lin - p * 10;
        unsigned pkp = __shfl_sync(0xffffffffu, pk, p);
        int J2p = (int)(pkp & 0xffu);
        int n4p = (int)(pkp >> 8);
        float4 v = __ldcs(corr4 + (size_t)(pix0 + p) * (W_ / 4) + (J2p + min(j, n4p)));
        float* dst = stw + p * 45 + 4 * j;
        dst[0] = v.x; dst[1] = v.y; dst[2] = v.z; dst[3] = v.w;
    }
    __syncwarp();

    const float* stf = stw + lane * 45;     // this thread's 40 raw floats

    int b = bh / H_;
    int h = bh - b * H_;
    int volBase = (b * 45 * H_ + h) * W_ + x;

    // ---- Level 0: window straight from staged raw ----
    // Upper clamp provably redundant: o0+9 = iF0+5-R0 <= 4*n4+3 <= 39.
    {
        int o0 = iF0 - 4 - R0;
        float w0_[10];
        #pragma unroll
        for (int i = 0; i < 10; ++i)
            w0_[i] = stf[max(o0 + i, 0)];
        sample_level(w0_, F0, c0, 319.0f, fx, out + volBase);
    }

    // ---- Level 1: pool pairs on the fly ----
    // Upper clamp provably redundant: o1+18+1 = 2*iF1+11-R0 <= 4*n4+3.
    {
        int o1 = 2 * (iF1 - 4) - R0;        // even; pairs (u, u+1)
        float w1_[10];
        #pragma unroll
        for (int i = 0; i < 10; ++i) {
            int u = max(o1 + 2 * i, 0);
            w1_[i] = __fmul_rn(__fadd_rn(stf[u], stf[u + 1]), 0.5f);
        }
        sample_level(w1_, F1, c1, 159.0f, __fmul_rn(fx, 0.5f), out + volBase + 15 * HWp);
    }

    // ---- Level 2: pairwise pool of 4 raw floats per slot ----
    {
        int o2 = iF2 - 4 - J2lo;            // in [-4, 0]
        float w2_[10];
        #pragma unroll
        for (int i = 0; i < 10; ++i) {
            int gg = max(o2 + i, 0);        // <= 9 always
            float s0 = __fmul_rn(__fadd_rn(stf[4*gg+0], stf[4*gg+1]), 0.5f);
            float s1 = __fmul_rn(__fadd_rn(stf[4*gg+2], stf[4*gg+3]), 0.5f);
            w2_[i] = __fmul_rn(__fadd_rn(s0, s1), 0.5f);
        }
        sample_level(w2_, F2, c2, 79.0f, __fmul_rn(fx, 0.25f), out + volBase + 30 * HWp);
    }
}

extern "C" void kernel_launch(void* const* d_in, const int* in_sizes, int n_in,
                              void* d_out, int out_size)
{
    const float* corr = (const float*)d_in[0];   // cross_attention [8,96,320,320]
    const float* disp = (const float*)d_in[1];   // cur_disp [8,1,96,320]
    float* out = (float*)d_out;                  // [vol ; disps], each [8,45,96,320]
    pcv_kernel<<<NVOLB + NDISPB, 128>>>(corr, disp, out);
}

// round 17
// speedup vs baseline: 1.1996x; 1.1568x over previous
#include <cuda_runtime.h>

// Problem shape (fixed by dataset instance)
#define B_   8
#define H_   96
#define W_   320
#define HWp  (H_ * W_)            // 30720
#define NPIX (B_ * HWp)           // 245760
#define VOL_ELEMS (B_ * 45 * HWp) // 11059200
#define INTERVAL (4.0f / 7.0f)
#define NVOLB  1920               // vol blocks (NPIX/128)
#define NDISPB 480                // disp blocks (NPIX/4/128)

// Sample one pyramid level from a register window w[0..9] (w[i] = level[F-4+i]).
// R10's proven numerics, unchanged.
__device__ __forceinline__ void sample_level(const float w[10],
                                             float Ff, float center, float w1m1,
                                             float stdv, float* __restrict__ outL)
{
    const int EL[8] = {0, 0, 1, 1, 2, 2, 3, 4};   // floor(s*4/7)
    float fm4 = __fsub_rn(Ff, 4.0f);
    float cm4 = __fsub_rn(center, 4.0f);
    float cp4 = __fadd_rn(center, 4.0f);

    #pragma unroll
    for (int s8 = 0; s8 < 8; ++s8) {
        const int e = EL[s8];
        float offs = __fmul_rn((float)s8, INTERVAL);

        // LEFT: floor(lc) in {F-4+e, F-4+e+1}; pick via exact float compare.
        float lc   = __fadd_rn(cm4, offs);
        float bnd0 = __fadd_rn(fm4, (float)e);
        float bnd1 = __fadd_rn(fm4, (float)(e + 1));
        bool  bl   = lc >= bnd1;
        float a    = bl ? w[e + 1] : w[e];
        float bb   = bl ? w[e + 2] : w[e + 1];
        float wt   = __fsub_rn(lc, bl ? bnd1 : bnd0);
        float v    = __fmaf_rn(wt, __fsub_rn(bb, a), a);
        outL[s8 * HWp] = (lc > 0.0f) ? v : 0.0f;

        // RIGHT: sample s -> channel 14-s; floor(c) in {F+3-e, F+4-e}.
        if (s8 < 7) {
            float rc = __fsub_rn(cp4, offs);
            float dn = __fsub_rn(stdv, rc);
            float c  = fminf(rc, w1m1);
            float r0 = __fadd_rn(Ff, (float)(3 - e));
            float r1 = __fadd_rn(Ff, (float)(4 - e));
            bool  br = c >= r1;
            float ar  = br ? w[8 - e] : w[7 - e];
            float bbr = br ? w[9 - e] : w[8 - e];
            float wr  = __fsub_rn(c, br ? r1 : r0);
            float vr  = __fmaf_rn(wr, __fsub_rn(bbr, ar), ar);
            outL[(14 - s8) * HWp] = (dn > 0.0f && dn < w1m1) ? vr : 0.0f;
        }
    }
}

__global__ void __launch_bounds__(128, 8)
pcv_kernel(const float* __restrict__ corr,
           const float* __restrict__ disp,
           float* __restrict__ out)
{
    int bid = blockIdx.x;
    int t   = threadIdx.x;

    // ---- Disp-writer blocks (interleaved 1-in-5): closed-form, float4 stores ----
    if (bid % 5 == 4) {
        int g  = (bid / 5) * 128 + t;          // quad index in [0, NPIX/4)
        int x4 = g % (W_ / 4);
        int bh = g / (W_ / 4);
        int x  = 4 * x4;
        float4 d4 = *reinterpret_cast<const float4*>(disp + bh * W_ + x);
        int b = bh / H_;
        int h = bh - b * H_;
        float* dst = out + VOL_ELEMS + ((size_t)(b * 45) * H_ + h) * W_ + x;
        #pragma unroll
        for (int lv = 0; lv < 3; ++lv) {
            float inv = (lv == 0) ? 1.0f : (lv == 1) ? 0.5f : 0.25f;
            float4 dl;
            dl.x = __fmul_rn(d4.x, inv); dl.y = __fmul_rn(d4.y, inv);
            dl.z = __fmul_rn(d4.z, inv); dl.w = __fmul_rn(d4.w, inv);
            #pragma unroll
            for (int c = 0; c < 15; ++c) {
                float kk = __fmul_rn((float)(c - 7), INTERVAL);
                float4 v;
                v.x = __fadd_rn(kk, dl.x); v.y = __fadd_rn(kk, dl.y);
                v.z = __fadd_rn(kk, dl.z); v.w = __fadd_rn(kk, dl.w);
                *reinterpret_cast<float4*>(dst + (size_t)(lv * 15 + c) * HWp) = v;
            }
        }
        return;
    }

    // ---- Vol blocks ----
    // Single staging buffer: 45-float stride per pixel (gcd(45,32)=1 ->
    // conflict-free scalar readback at uniform offsets). 22.5 KB -> 8 blocks/SM.
    __shared__ float stageS[128 * 45];

    int lane = t & 31;
    int warp = t >> 5;

    int vbid = (bid / 5) * 4 + (bid % 5);   // [0, 1920)
    int idx  = vbid * 128 + t;

    int x  = idx % W_;
    int bh = idx / W_;
    float d  = __ldg(disp + idx);
    float fx = (float)x;

    // centers per level: clip(x/2^i - d/2^i, 0, w1-1)
    float c0 = fminf(fmaxf(__fsub_rn(fx, d), 0.0f), 319.0f);
    float c1 = fminf(fmaxf(__fsub_rn(__fmul_rn(fx, 0.5f),  __fmul_rn(d, 0.5f)),  0.0f), 159.0f);
    float c2 = fminf(fmaxf(__fsub_rn(__fmul_rn(fx, 0.25f), __fmul_rn(d, 0.25f)), 0.0f), 79.0f);

    float F0 = floorf(c0), F1 = floorf(c1), F2 = floorf(c2);
    int iF0 = (int)F0, iF1 = (int)F1, iF2 = (int)F2;

    int J2lo = max(0, iF2 - 4);
    int J2hi = min(79, (int)ceilf(c2) + 4);
    int n4   = J2hi - J2lo;                 // 4..9
    int J1lo = max(0, iF1 - 4);
    int R0   = 4 * J2lo;

    // ---- Cooperative warp gather: lanes fetch consecutive float4s of the same
    // pixel's window (contiguous lines; ~7 lines/instr instead of 32).
    // (pixel, j) = (lin/10, lin%10); per-target params via shfl. All 10 slots of
    // every pixel get written (clamped source) -> staging is always finite.
    float* stw = stageS + warp * (32 * 45);
    unsigned pk = (unsigned)J2lo | ((unsigned)n4 << 8);
    int pix0 = vbid * 128 + (t & ~31);
    const float4* corr4 = reinterpret_cast<const float4*>(corr);

    #pragma unroll
    for (int it = 0; it < 10; ++it) {
        int lin = it * 32 + lane;           // 0..319
        int p   = lin / 10;
        int j   = lin - p * 10;
        unsigned pkp = __shfl_sync(0xffffffffu, pk, p);
        int J2p = (int)(pkp & 0xffu);
        int n4p = (int)(pkp >> 8);
        float4 v = __ldcs(corr4 + (size_t)(pix0 + p) * (W_ / 4) + (J2p + min(j, n4p)));
        float* dst = stw + p * 45 + 4 * j;
        dst[0] = v.x; dst[1] = v.y; dst[2] = v.z; dst[3] = v.w;
    }
    __syncwarp();

    const float* stf = stw + lane * 45;     // this thread's 40 raw floats

    int b = bh / H_;
    int h = bh - b * H_;
    int volBase = (b * 45 * H_ + h) * W_ + x;

    // ---- Level 0: window straight from staged raw ----
    {
        int o0 = iF0 - 4 - R0;              // valid reads within true data (proof R4-R10)
        float w0_[10];
        #pragma unroll
        for (int i = 0; i < 10; ++i)
            w0_[i] = stf[min(max(o0 + i, 0), 39)];
        sample_level(w0_, F0, c0, 319.0f, fx, out + volBase);
    }

    // ---- Level 1: pool pairs on the fly (identical arithmetic to prior rounds) ----
    {
        int o1 = 2 * (iF1 - 4) - R0;        // even; pairs (u, u+1)
        float w1_[10];
        #pragma unroll
        for (int i = 0; i < 10; ++i) {
            int u = min(max(o1 + 2 * i, 0), 38);
            w1_[i] = __fmul_rn(__fadd_rn(stf[u], stf[u + 1]), 0.5f);
        }
        sample_level(w1_, F1, c1, 159.0f, __fmul_rn(fx, 0.5f), out + volBase + 15 * HWp);
    }

    // ---- Level 2: pairwise pool of 4 raw floats per slot ----
    {
        int o2 = iF2 - 4 - J2lo;            // in [-4, 0]
        float w2_[10];
        #pragma unroll
        for (int i = 0; i < 10; ++i) {
            int gg = max(o2 + i, 0);        // <= 9 always
            float s0 = __fmul_rn(__fadd_rn(stf[4*gg+0], stf[4*gg+1]), 0.5f);
            float s1 = __fmul_rn(__fadd_rn(stf[4*gg+2], stf[4*gg+3]), 0.5f);
            w2_[i] = __fmul_rn(__fadd_rn(s0, s1), 0.5f);
        }
        sample_level(w2_, F2, c2, 79.0f, __fmul_rn(fx, 0.25f), out + volBase + 30 * HWp);
    }
}

extern "C" void kernel_launch(void* const* d_in, const int* in_sizes, int n_in,
                              void* d_out, int out_size)
{
    const float* corr = (const float*)d_in[0];   // cross_attention [8,96,320,320]
    const float* disp = (const float*)d_in[1];   // cur_disp [8,1,96,320]
    float* out = (float*)d_out;                  // [vol ; disps], each [8,45,96,320]
    pcv_kernel<<<NVOLB + NDISPB, 128>>>(corr, disp, out);
}